// round 1
// baseline (speedup 1.0000x reference)
#include <cuda_runtime.h>
#include <cstddef>

#define Hd   50
#define HP   51      // padded row stride (odd -> conflict-free smem)
#define G4   200     // 4*H
#define Bsz  4096
#define Tt   256
#define EPB  16      // elements per block
#define EPT  4       // elements per thread
#define NTHR 200     // 50 units * 4 element-groups

// Ping-pong inter-layer activations: [T][B][H] fp32
__device__ float g_ysA[(size_t)Tt * Bsz * Hd];
__device__ float g_ysB[(size_t)Tt * Bsz * Hd];

__device__ __forceinline__ float sigf(float x) {
    // 1/(1+exp(-x)) via MUFU.EX2; accurate to ~1e-7 rel
    return __fdividef(1.0f, 1.0f + __expf(-x));
}
__device__ __forceinline__ float tanhf_fast(float x) {
    // tanh(x) = 1 - 2/(exp(2x)+1); saturates correctly at +/-inf
    return 1.0f - __fdividef(2.0f, __expf(2.0f * x) + 1.0f);
}

// One LSTM layer over the full sequence for a tile of 16 batch elements.
// layer0 != 0: input is x [B][T][1] (w_ih is [200][1], stored at Wi[g*HP+50]).
// Otherwise input is ys_in [T][B][H], w_ih [200][50].
// If out != nullptr, also computes out[e] = fc(h_T) (last layer).
__global__ __launch_bounds__(NTHR, 2)
void lstm_layer_kernel(const float* __restrict__ x,
                       const float* __restrict__ ys_in,
                       const float* __restrict__ w_ih,
                       const float* __restrict__ w_hh,
                       const float* __restrict__ bias,
                       float* __restrict__ ys_out,
                       const float* __restrict__ fc_w,
                       const float* __restrict__ fc_b,
                       float* __restrict__ out,
                       int layer0)
{
    extern __shared__ float sm[];
    float* Wh  = sm;                    // [200][HP]
    float* Wi  = Wh + G4 * HP;          // [200][HP] (col 50 holds w_ih0 for layer0)
    float* bia = Wi + G4 * HP;          // [200]
    float* h_s = bia + G4;              // [16][HP]
    float* in_s = h_s + EPB * HP;       // [16][HP]

    const int tid = threadIdx.x;
    const int e0  = blockIdx.x * EPB;

    // ---- load weights into smem (once per pass) ----
    for (int idx = tid; idx < G4 * Hd; idx += NTHR) {
        int g = idx / Hd, j = idx % Hd;
        Wh[g * HP + j] = w_hh[idx];
        Wi[g * HP + j] = layer0 ? 0.0f : w_ih[idx];
    }
    for (int idx = tid; idx < G4; idx += NTHR) {
        bia[idx] = bias[idx];
        if (layer0) Wi[idx * HP + 50] = w_ih[idx];  // [200][1]
    }
    // ---- init state ----
    for (int idx = tid; idx < EPB * HP; idx += NTHR) h_s[idx] = 0.0f;

    const int u     = tid % Hd;     // hidden unit 0..49
    const int eg    = tid / Hd;     // element group 0..3
    const int ebase = eg * EPT;

    const float* wri = Wh + (u)        * HP;
    const float* wrf = Wh + (50 + u)   * HP;
    const float* wrg = Wh + (100 + u)  * HP;
    const float* wro = Wh + (150 + u)  * HP;
    const float* vri = Wi + (u)        * HP;
    const float* vrf = Wi + (50 + u)   * HP;
    const float* vrg = Wi + (100 + u)  * HP;
    const float* vro = Wi + (150 + u)  * HP;

    float c[EPT];
    #pragma unroll
    for (int e = 0; e < EPT; e++) c[e] = 0.0f;

    const float bi = bias[u], bf = bias[50 + u], bg = bias[100 + u], bo = bias[150 + u];

    __syncthreads();

    for (int t = 0; t < Tt; t++) {
        // ---- stage input for this timestep ----
        if (layer0) {
            if (tid < EPB) in_s[tid * HP] = x[(size_t)(e0 + tid) * Tt + t];
        } else {
            const float* src = ys_in + ((size_t)t * Bsz + e0) * Hd;
            for (int idx = tid; idx < EPB * Hd; idx += NTHR) {
                int e = idx / Hd, j = idx % Hd;
                in_s[e * HP + j] = src[idx];
            }
        }
        __syncthreads();   // in_s ready; previous h_s writes visible

        float ai[EPT], af[EPT], ag[EPT], ao[EPT];
        #pragma unroll
        for (int e = 0; e < EPT; e++) { ai[e] = bi; af[e] = bf; ag[e] = bg; ao[e] = bo; }

        // ---- recurrent dot: h(t-1) @ W_hh^T ----
        #pragma unroll 10
        for (int j = 0; j < Hd; j++) {
            float wi = wri[j], wf = wrf[j], wg = wrg[j], wo = wro[j];
            float h0 = h_s[(ebase + 0) * HP + j];
            float h1 = h_s[(ebase + 1) * HP + j];
            float h2 = h_s[(ebase + 2) * HP + j];
            float h3 = h_s[(ebase + 3) * HP + j];
            ai[0] += wi * h0; ai[1] += wi * h1; ai[2] += wi * h2; ai[3] += wi * h3;
            af[0] += wf * h0; af[1] += wf * h1; af[2] += wf * h2; af[3] += wf * h3;
            ag[0] += wg * h0; ag[1] += wg * h1; ag[2] += wg * h2; ag[3] += wg * h3;
            ao[0] += wo * h0; ao[1] += wo * h1; ao[2] += wo * h2; ao[3] += wo * h3;
        }

        // ---- input dot ----
        if (layer0) {
            float wi = vri[50], wf = vrf[50], wg = vrg[50], wo = vro[50];
            #pragma unroll
            for (int e = 0; e < EPT; e++) {
                float xv = in_s[(ebase + e) * HP];
                ai[e] += wi * xv; af[e] += wf * xv; ag[e] += wg * xv; ao[e] += wo * xv;
            }
        } else {
            #pragma unroll 10
            for (int j = 0; j < Hd; j++) {
                float wi = vri[j], wf = vrf[j], wg = vrg[j], wo = vro[j];
                float x0 = in_s[(ebase + 0) * HP + j];
                float x1 = in_s[(ebase + 1) * HP + j];
                float x2 = in_s[(ebase + 2) * HP + j];
                float x3 = in_s[(ebase + 3) * HP + j];
                ai[0] += wi * x0; ai[1] += wi * x1; ai[2] += wi * x2; ai[3] += wi * x3;
                af[0] += wf * x0; af[1] += wf * x1; af[2] += wf * x2; af[3] += wf * x3;
                ag[0] += wg * x0; ag[1] += wg * x1; ag[2] += wg * x2; ag[3] += wg * x3;
                ao[0] += wo * x0; ao[1] += wo * x1; ao[2] += wo * x2; ao[3] += wo * x3;
            }
        }

        __syncthreads();   // everyone done reading old h_s

        // ---- gate nonlinearities + state update; this thread owns h(e, u) ----
        #pragma unroll
        for (int e = 0; e < EPT; e++) {
            float iv = sigf(ai[e]);
            float fv = sigf(af[e]);
            float gv = tanhf_fast(ag[e]);
            float ov = sigf(ao[e]);
            c[e] = fv * c[e] + iv * gv;
            float hv = ov * tanhf_fast(c[e]);
            h_s[(ebase + e) * HP + u] = hv;
            if (ys_out) ys_out[((size_t)t * Bsz + e0 + ebase + e) * Hd + u] = hv;
        }
    }

    // ---- FC head on final hidden state (last layer only) ----
    if (out != nullptr) {
        __syncthreads();
        if (tid < EPB) {
            float s = fc_b[0];
            #pragma unroll 10
            for (int j = 0; j < Hd; j++) s += h_s[tid * HP + j] * fc_w[j];
            out[e0 + tid] = s;
        }
    }
}

extern "C" void kernel_launch(void* const* d_in, const int* in_sizes, int n_in,
                              void* d_out, int out_size)
{
    const float* x     = (const float*)d_in[0];  // [B,T,1]
    const float* w_ih0 = (const float*)d_in[1];  // [200,1]
    const float* w_hh0 = (const float*)d_in[2];  // [200,50]
    const float* b0    = (const float*)d_in[3];  // [200]
    const float* w_ih  = (const float*)d_in[4];  // [4,200,50]
    const float* w_hh  = (const float*)d_in[5];  // [4,200,50]
    const float* b     = (const float*)d_in[6];  // [4,200]
    const float* fc_w  = (const float*)d_in[7];  // [1,50]
    const float* fc_b  = (const float*)d_in[8];  // [1]
    float* out = (float*)d_out;

    float *ysA = nullptr, *ysB = nullptr;
    cudaGetSymbolAddress((void**)&ysA, g_ysA);
    cudaGetSymbolAddress((void**)&ysB, g_ysB);

    const int smem = (2 * G4 * HP + G4 + 2 * EPB * HP) * (int)sizeof(float);
    cudaFuncSetAttribute(lstm_layer_kernel,
                         cudaFuncAttributeMaxDynamicSharedMemorySize, smem);

    const dim3 grid(Bsz / EPB);   // 256 blocks
    const dim3 block(NTHR);       // 200 threads

    // Layer 0: input x (Din=1) -> ysA
    lstm_layer_kernel<<<grid, block, smem>>>(
        x, nullptr, w_ih0, w_hh0, b0, ysA, nullptr, nullptr, nullptr, 1);

    // Layers 1..3: ping-pong ysA/ysB
    const float* src = ysA;
    float* dst = ysB;
    for (int l = 0; l < 3; l++) {
        lstm_layer_kernel<<<grid, block, smem>>>(
            nullptr, src, w_ih + (size_t)l * G4 * Hd, w_hh + (size_t)l * G4 * Hd,
            b + (size_t)l * G4, dst, nullptr, nullptr, nullptr, 0);
        const float* tmp = dst; dst = (float*)src; src = tmp;
    }

    // Layer 4 (l=3 of the stacked array): no ys_out, fused FC head -> out
    lstm_layer_kernel<<<grid, block, smem>>>(
        nullptr, src, w_ih + (size_t)3 * G4 * Hd, w_hh + (size_t)3 * G4 * Hd,
        b + (size_t)3 * G4, nullptr, fc_w, fc_b, out, 0);
}